// round 9
// baseline (speedup 1.0000x reference)
#include <cuda_runtime.h>
#include <math.h>

#define D_MODEL 1024
#define N_HEAD  16
#define DK      64
#define SEQ     2048
#define MAXROWS 4096

// Scratch (allocation-free rule: __device__ globals)
__device__ float g_q[MAXROWS * D_MODEL];
__device__ float g_k[MAXROWS * D_MODEL];
__device__ float g_v[MAXROWS * D_MODEL];
__device__ float g_att[MAXROWS * D_MODEL];

// ---------------------------------------------------------------------------
// SGEMM body: C[M,N] = A[M,K] @ W[N,K]^T + bias[N], N = K = 1024.
// BM=BN=128, BK=8, 256 threads, 8x8 per-thread tile, register-staged pipeline.
// ---------------------------------------------------------------------------
__device__ __forceinline__ void gemm_body(const float* __restrict__ A,
                                          const float* __restrict__ W,
                                          const float* __restrict__ bias,
                                          float* __restrict__ C, int M) {
    __shared__ float As[8][128];
    __shared__ float Bs[8][128];

    const int tid = threadIdx.x;
    const int tx = tid & 15;
    const int ty = tid >> 4;
    const int m0 = blockIdx.y * 128;
    const int n0 = blockIdx.x * 128;

    const int lrow = tid >> 1;         // 0..127
    const int lk4  = (tid & 1) * 4;    // 0 or 4

    const float* Aptr = A + (m0 + lrow) * D_MODEL + lk4;
    const float* Wptr = W + (n0 + lrow) * D_MODEL + lk4;

    float acc[8][8];
#pragma unroll
    for (int i = 0; i < 8; i++)
#pragma unroll
        for (int j = 0; j < 8; j++) acc[i][j] = 0.f;

    float4 ra = *(const float4*)Aptr;
    float4 rb = *(const float4*)Wptr;

    const int NT = D_MODEL / 8;  // 128 k-tiles
    for (int kt = 0; kt < NT; kt++) {
        As[lk4 + 0][lrow] = ra.x; As[lk4 + 1][lrow] = ra.y;
        As[lk4 + 2][lrow] = ra.z; As[lk4 + 3][lrow] = ra.w;
        Bs[lk4 + 0][lrow] = rb.x; Bs[lk4 + 1][lrow] = rb.y;
        Bs[lk4 + 2][lrow] = rb.z; Bs[lk4 + 3][lrow] = rb.w;
        __syncthreads();

        if (kt + 1 < NT) {  // prefetch next tile into regs (overlaps compute)
            ra = *(const float4*)(Aptr + (kt + 1) * 8);
            rb = *(const float4*)(Wptr + (kt + 1) * 8);
        }

#pragma unroll
        for (int k = 0; k < 8; k++) {
            float4 a0 = *(const float4*)&As[k][ty * 4];
            float4 a1 = *(const float4*)&As[k][64 + ty * 4];
            float4 b0 = *(const float4*)&Bs[k][tx * 4];
            float4 b1 = *(const float4*)&Bs[k][64 + tx * 4];
            float a[8] = {a0.x, a0.y, a0.z, a0.w, a1.x, a1.y, a1.z, a1.w};
            float b[8] = {b0.x, b0.y, b0.z, b0.w, b1.x, b1.y, b1.z, b1.w};
#pragma unroll
            for (int i = 0; i < 8; i++)
#pragma unroll
                for (int j = 0; j < 8; j++)
                    acc[i][j] = fmaf(a[i], b[j], acc[i][j]);
        }
        __syncthreads();
    }

    float4 bias0 = *(const float4*)&bias[n0 + tx * 4];
    float4 bias1 = *(const float4*)&bias[n0 + 64 + tx * 4];
#pragma unroll
    for (int i = 0; i < 8; i++) {
        int r = m0 + ((i < 4) ? (ty * 4 + i) : (64 + ty * 4 + i - 4));
        float4 o0, o1;
        o0.x = acc[i][0] + bias0.x; o0.y = acc[i][1] + bias0.y;
        o0.z = acc[i][2] + bias0.z; o0.w = acc[i][3] + bias0.w;
        o1.x = acc[i][4] + bias1.x; o1.y = acc[i][5] + bias1.y;
        o1.z = acc[i][6] + bias1.z; o1.w = acc[i][7] + bias1.w;
        *(float4*)&C[r * D_MODEL + n0 + tx * 4] = o0;
        *(float4*)&C[r * D_MODEL + n0 + 64 + tx * 4] = o1;
    }
}

__global__ __launch_bounds__(256) void qkv_gemm_kernel(
    const float* __restrict__ q_in, const float* __restrict__ k_in,
    const float* __restrict__ v_in,
    const float* __restrict__ Wq, const float* __restrict__ bq,
    const float* __restrict__ Wk, const float* __restrict__ bk,
    const float* __restrict__ Wv, const float* __restrict__ bv, int M) {
    const float *A, *W, *bias;
    float* C;
    if (blockIdx.z == 0)      { A = q_in; W = Wq; bias = bq; C = g_q; }
    else if (blockIdx.z == 1) { A = k_in; W = Wk; bias = bk; C = g_k; }
    else                      { A = v_in; W = Wv; bias = bv; C = g_v; }
    gemm_body(A, W, bias, C, M);
}

__global__ __launch_bounds__(256) void out_gemm_kernel(
    const float* __restrict__ Wo, const float* __restrict__ bo,
    float* __restrict__ out, int M) {
    gemm_body(g_att, Wo, bo, out, M);
}

// ---------------------------------------------------------------------------
// Flash attention: block = (b, h, 128-row q-tile), 256 threads (16x16),
// 8x4 per-thread fragments (rows ty+16*i, i<8; cols tx+16*j, j<4),
// 64-row KV tiles, online softmax. Softmax scale folded into Q load.
// Fragment loads chunked 4-at-a-time to bound register pressure.
// smem: Qs[128][68] + Ks[64][68] + Vs[64][64] + Ps[128][68] = 103424 B.
// ---------------------------------------------------------------------------
#define QS 68  // padded stride

__global__ __launch_bounds__(256) void attn_kernel() {
    extern __shared__ float sm[];
    float* Qs = sm;                            // 128*68
    float* Ks = Qs + 128 * QS;                 // 64*68
    float* Vs = Ks + 64 * QS;                  // 64*64
    float* Ps = Vs + 64 * 64;                  // 128*68

    const int tid = threadIdx.x;
    const int tx = tid & 15;
    const int ty = tid >> 4;
    const int q0 = blockIdx.x * 128;
    const int h  = blockIdx.y;
    const int b  = blockIdx.z;
    const int base = b * SEQ * D_MODEL + h * DK;

    // Load Q tile (128 rows x 64 dk) -> Qs (stride 68), scale folded in
    for (int f = tid; f < 128 * 16; f += 256) {
        int i = f >> 4, d4 = (f & 15) << 2;
        float4 qv = *(const float4*)&g_q[base + (q0 + i) * D_MODEL + d4];
        qv.x *= 0.125f; qv.y *= 0.125f; qv.z *= 0.125f; qv.w *= 0.125f;
        *(float4*)&Qs[i * QS + d4] = qv;
    }

    float acc[8][4];
    float m[8], l[8];
#pragma unroll
    for (int i = 0; i < 8; i++) {
        m[i] = -1e30f; l[i] = 0.f;
#pragma unroll
        for (int j = 0; j < 4; j++) acc[i][j] = 0.f;
    }

    for (int kt = 0; kt < SEQ / 64; kt++) {
        const int kv0 = kt * 64;
        __syncthreads();  // previous iter done reading Ks/Vs/Ps
        for (int f = tid; f < 64 * 16; f += 256) {
            int j = f >> 4, d4 = (f & 15) << 2;
            *(float4*)&Ks[j * QS + d4] =
                *(const float4*)&g_k[base + (kv0 + j) * D_MODEL + d4];
            *(float4*)&Vs[j * 64 + d4] =
                *(const float4*)&g_v[base + (kv0 + j) * D_MODEL + d4];
        }
        __syncthreads();

        // S = (Q*scale) @ K^T ; rows r=ty+16*i (i<8), cols c=tx+16*j (j<4)
        float s[8][4];
#pragma unroll
        for (int i = 0; i < 8; i++)
#pragma unroll
            for (int j = 0; j < 4; j++) s[i][j] = 0.f;

#pragma unroll 4
        for (int d4 = 0; d4 < 16; d4++) {
            float4 kv[4];
#pragma unroll
            for (int j = 0; j < 4; j++)
                kv[j] = *(const float4*)&Ks[(tx + 16 * j) * QS + 4 * d4];
            // chunk q-rows 4 at a time to bound live registers
#pragma unroll
            for (int ic = 0; ic < 2; ic++) {
                float4 qv[4];
#pragma unroll
                for (int i = 0; i < 4; i++)
                    qv[i] = *(const float4*)&Qs[(ty + 16 * (4 * ic + i)) * QS + 4 * d4];
#pragma unroll
                for (int i = 0; i < 4; i++) {
                    int ii = 4 * ic + i;
#pragma unroll
                    for (int j = 0; j < 4; j++) {
                        s[ii][j] = fmaf(qv[i].x, kv[j].x, s[ii][j]);
                        s[ii][j] = fmaf(qv[i].y, kv[j].y, s[ii][j]);
                        s[ii][j] = fmaf(qv[i].z, kv[j].z, s[ii][j]);
                        s[ii][j] = fmaf(qv[i].w, kv[j].w, s[ii][j]);
                    }
                }
            }
        }

        // online softmax (row c-reduction across the 16 tx lanes, width 16)
#pragma unroll
        for (int i = 0; i < 8; i++) {
            float mx = fmaxf(fmaxf(s[i][0], s[i][1]), fmaxf(s[i][2], s[i][3]));
#pragma unroll
            for (int o = 8; o; o >>= 1)
                mx = fmaxf(mx, __shfl_xor_sync(0xffffffffu, mx, o, 16));
            float mn = fmaxf(m[i], mx);
            float corr = __expf(m[i] - mn);
            m[i] = mn;
            float sum = 0.f;
#pragma unroll
            for (int j = 0; j < 4; j++) {
                float p = __expf(s[i][j] - mn);
                s[i][j] = p;
                sum += p;
            }
#pragma unroll
            for (int o = 8; o; o >>= 1)
                sum += __shfl_xor_sync(0xffffffffu, sum, o, 16);
            l[i] = l[i] * corr + sum;
#pragma unroll
            for (int j = 0; j < 4; j++) acc[i][j] *= corr;
        }

        // write P (128 x 64) to its own buffer; no aliasing with Ks
#pragma unroll
        for (int i = 0; i < 8; i++)
#pragma unroll
            for (int j = 0; j < 4; j++)
                Ps[(ty + 16 * i) * QS + (tx + 16 * j)] = s[i][j];
        __syncthreads();

        // O += P @ V ; O cols d = tx + 16*j (dk dim), chunked like S-loop
#pragma unroll 4
        for (int j4 = 0; j4 < 16; j4++) {
            float vf[4][4];  // vf[u][j]
#pragma unroll
            for (int u = 0; u < 4; u++)
#pragma unroll
                for (int j = 0; j < 4; j++)
                    vf[u][j] = Vs[(4 * j4 + u) * 64 + tx + 16 * j];
#pragma unroll
            for (int ic = 0; ic < 2; ic++) {
                float4 pv[4];
#pragma unroll
                for (int i = 0; i < 4; i++)
                    pv[i] = *(const float4*)&Ps[(ty + 16 * (4 * ic + i)) * QS + 4 * j4];
#pragma unroll
                for (int u = 0; u < 4; u++) {
#pragma unroll
                    for (int i = 0; i < 4; i++) {
                        int ii = 4 * ic + i;
                        float p = ((const float*)&pv[i])[u];
#pragma unroll
                        for (int j = 0; j < 4; j++)
                            acc[ii][j] = fmaf(p, vf[u][j], acc[ii][j]);
                    }
                }
            }
        }
        __syncthreads();  // all PV reads done before next iter overwrites Ks/Vs/Ps
    }

    // normalize + store (heads merged back into [B,S,D_MODEL])
#pragma unroll
    for (int i = 0; i < 8; i++) {
        float inv = 1.f / l[i];
        int r = q0 + ty + 16 * i;
#pragma unroll
        for (int j = 0; j < 4; j++)
            g_att[base + r * D_MODEL + tx + 16 * j] = acc[i][j] * inv;
    }
}

// ---------------------------------------------------------------------------
extern "C" void kernel_launch(void* const* d_in, const int* in_sizes, int n_in,
                              void* d_out, int out_size) {
    const float* query = (const float*)d_in[0];
    const float* key   = (const float*)d_in[1];
    const float* value = (const float*)d_in[2];
    const float* Wq = (const float*)d_in[3];
    const float* bq = (const float*)d_in[4];
    const float* Wk = (const float*)d_in[5];
    const float* bk = (const float*)d_in[6];
    const float* Wv = (const float*)d_in[7];
    const float* bv = (const float*)d_in[8];
    const float* Wo = (const float*)d_in[9];
    const float* bo = (const float*)d_in[10];

    const int M = in_sizes[0] / D_MODEL;  // B*S = 4096
    const int B = M / SEQ;

    dim3 g1(D_MODEL / 128, M / 128, 3);
    qkv_gemm_kernel<<<g1, 256>>>(query, key, value, Wq, bq, Wk, bk, Wv, bv, M);

    // Qs 128*68 + Ks 64*68 + Vs 64*64 + Ps 128*68 floats = 103424 bytes
    size_t shmem =
        (size_t)(128 * QS + 64 * QS + 64 * 64 + 128 * QS) * sizeof(float);
    cudaFuncSetAttribute(attn_kernel,
                         cudaFuncAttributeMaxDynamicSharedMemorySize,
                         (int)shmem);
    dim3 g2(SEQ / 128, N_HEAD, B);
    attn_kernel<<<g2, 256, shmem>>>();

    dim3 g3(D_MODEL / 128, M / 128, 1);
    out_gemm_kernel<<<g3, 256>>>(Wo, bo, (float*)d_out, M);
}

// round 10
// speedup vs baseline: 1.0567x; 1.0567x over previous
#include <cuda_runtime.h>
#include <math.h>
#include <stdint.h>

#define D_MODEL 1024
#define N_HEAD  16
#define DK      64
#define SEQ     2048
#define MAXROWS 4096

// Scratch (allocation-free rule: __device__ globals)
__device__ float g_q[MAXROWS * D_MODEL];
__device__ float g_k[MAXROWS * D_MODEL];
__device__ float g_v[MAXROWS * D_MODEL];
__device__ float g_att[MAXROWS * D_MODEL];

// ---------------------------------------------------------------------------
// tf32 helpers
// ---------------------------------------------------------------------------
__device__ __forceinline__ float tf32_rna(float x) {
    uint32_t u;
    asm("cvt.rna.tf32.f32 %0, %1;" : "=r"(u) : "f"(x));
    return __uint_as_float(u);
}

__device__ __forceinline__ void mma_tf32(float* c, const uint32_t* a,
                                         const uint32_t* b) {
    asm volatile(
        "mma.sync.aligned.m16n8k8.row.col.f32.tf32.tf32.f32 "
        "{%0,%1,%2,%3}, {%4,%5,%6,%7}, {%8,%9}, {%0,%1,%2,%3};\n"
        : "+f"(c[0]), "+f"(c[1]), "+f"(c[2]), "+f"(c[3])
        : "r"(a[0]), "r"(a[1]), "r"(a[2]), "r"(a[3]), "r"(b[0]), "r"(b[1]));
}

// ---------------------------------------------------------------------------
// 3xTF32 GEMM: C[M,N] = A[M,K] @ W[N,K]^T + bias, N=K=1024.
// BM=BN=128, BK=16, 256 threads = 8 warps (2x4), warp tile 64x32,
// mma m16n8k8, accuracy ~fp32 via hi/lo split (3 MMAs per tile).
// smem tiles stored [row][k] with stride 20 (conflict-free fragment loads).
// ---------------------------------------------------------------------------
#define AST 20

__device__ __forceinline__ void split_store(float* hp, float* lp, float4 v) {
    float h0 = tf32_rna(v.x), h1 = tf32_rna(v.y);
    float h2 = tf32_rna(v.z), h3 = tf32_rna(v.w);
    *(float4*)hp = make_float4(h0, h1, h2, h3);
    *(float4*)lp = make_float4(v.x - h0, v.y - h1, v.z - h2, v.w - h3);
}

__device__ __forceinline__ void gemm3x_body(const float* __restrict__ A,
                                            const float* __restrict__ W,
                                            const float* __restrict__ bias,
                                            float* __restrict__ C) {
    __shared__ float Ah[128][AST], Al[128][AST];
    __shared__ float Wh[128][AST], Wl[128][AST];

    const int tid = threadIdx.x;
    const int lane = tid & 31;
    const int wid = tid >> 5;
    const int g = lane >> 2, tg = lane & 3;
    const int wr = wid >> 2;         // warp row 0..1 (64 rows each)
    const int wc = wid & 3;          // warp col 0..3 (32 cols each)
    const int m0 = blockIdx.y * 128;
    const int n0 = blockIdx.x * 128;

    const int r0 = tid >> 2;             // 0..63
    const int kq = (tid & 3) << 2;       // 0,4,8,12

    float acc[4][4][4];
#pragma unroll
    for (int mi = 0; mi < 4; mi++)
#pragma unroll
        for (int ni = 0; ni < 4; ni++)
#pragma unroll
            for (int r = 0; r < 4; r++) acc[mi][ni][r] = 0.f;

    const float* Ap0 = A + (m0 + r0) * D_MODEL + kq;
    const float* Ap1 = A + (m0 + r0 + 64) * D_MODEL + kq;
    const float* Wp0 = W + (n0 + r0) * D_MODEL + kq;
    const float* Wp1 = W + (n0 + r0 + 64) * D_MODEL + kq;

    float4 ra0 = *(const float4*)Ap0;
    float4 ra1 = *(const float4*)Ap1;
    float4 rw0 = *(const float4*)Wp0;
    float4 rw1 = *(const float4*)Wp1;

    const int NT = D_MODEL / 16;  // 64 k-chunks
    for (int kt = 0; kt < NT; kt++) {
        __syncthreads();  // prev iter finished reading smem (no-op at kt=0)
        split_store(&Ah[r0][kq],      &Al[r0][kq],      ra0);
        split_store(&Ah[r0 + 64][kq], &Al[r0 + 64][kq], ra1);
        split_store(&Wh[r0][kq],      &Wl[r0][kq],      rw0);
        split_store(&Wh[r0 + 64][kq], &Wl[r0 + 64][kq], rw1);
        __syncthreads();

        if (kt + 1 < NT) {  // prefetch next chunk (overlaps MMA)
            ra0 = *(const float4*)(Ap0 + (kt + 1) * 16);
            ra1 = *(const float4*)(Ap1 + (kt + 1) * 16);
            rw0 = *(const float4*)(Wp0 + (kt + 1) * 16);
            rw1 = *(const float4*)(Wp1 + (kt + 1) * 16);
        }

#pragma unroll
        for (int ks = 0; ks < 16; ks += 8) {
            uint32_t ahi[4][4], alo[4][4];
#pragma unroll
            for (int mi = 0; mi < 4; mi++) {
                int mb = wr * 64 + mi * 16;
                ahi[mi][0] = __float_as_uint(Ah[mb + g][ks + tg]);
                ahi[mi][1] = __float_as_uint(Ah[mb + g + 8][ks + tg]);
                ahi[mi][2] = __float_as_uint(Ah[mb + g][ks + tg + 4]);
                ahi[mi][3] = __float_as_uint(Ah[mb + g + 8][ks + tg + 4]);
                alo[mi][0] = __float_as_uint(Al[mb + g][ks + tg]);
                alo[mi][1] = __float_as_uint(Al[mb + g + 8][ks + tg]);
                alo[mi][2] = __float_as_uint(Al[mb + g][ks + tg + 4]);
                alo[mi][3] = __float_as_uint(Al[mb + g + 8][ks + tg + 4]);
            }
#pragma unroll
            for (int ni = 0; ni < 4; ni++) {
                int nb = wc * 32 + ni * 8;
                uint32_t bh[2], bl[2];
                bh[0] = __float_as_uint(Wh[nb + g][ks + tg]);
                bh[1] = __float_as_uint(Wh[nb + g][ks + tg + 4]);
                bl[0] = __float_as_uint(Wl[nb + g][ks + tg]);
                bl[1] = __float_as_uint(Wl[nb + g][ks + tg + 4]);
#pragma unroll
                for (int mi = 0; mi < 4; mi++) {
                    mma_tf32(acc[mi][ni], ahi[mi], bh);
                    mma_tf32(acc[mi][ni], ahi[mi], bl);
                    mma_tf32(acc[mi][ni], alo[mi], bh);
                }
            }
        }
    }

    // epilogue: bias + store (c0,c1 at (row,col..col+1); c2,c3 at row+8)
#pragma unroll
    for (int mi = 0; mi < 4; mi++) {
        int row = m0 + wr * 64 + mi * 16 + g;
#pragma unroll
        for (int ni = 0; ni < 4; ni++) {
            int col = n0 + wc * 32 + ni * 8 + 2 * tg;
            float b0 = bias[col], b1 = bias[col + 1];
            float2 v0 = make_float2(acc[mi][ni][0] + b0, acc[mi][ni][1] + b1);
            float2 v1 = make_float2(acc[mi][ni][2] + b0, acc[mi][ni][3] + b1);
            *(float2*)&C[row * D_MODEL + col] = v0;
            *(float2*)&C[(row + 8) * D_MODEL + col] = v1;
        }
    }
}

__global__ __launch_bounds__(256) void qkv_gemm_kernel(
    const float* __restrict__ q_in, const float* __restrict__ k_in,
    const float* __restrict__ v_in,
    const float* __restrict__ Wq, const float* __restrict__ bq,
    const float* __restrict__ Wk, const float* __restrict__ bk,
    const float* __restrict__ Wv, const float* __restrict__ bv) {
    const float *A, *W, *bias;
    float* C;
    if (blockIdx.z == 0)      { A = q_in; W = Wq; bias = bq; C = g_q; }
    else if (blockIdx.z == 1) { A = k_in; W = Wk; bias = bk; C = g_k; }
    else                      { A = v_in; W = Wv; bias = bv; C = g_v; }
    gemm3x_body(A, W, bias, C);
}

__global__ __launch_bounds__(256) void out_gemm_kernel(
    const float* __restrict__ Wo, const float* __restrict__ bo,
    float* __restrict__ out) {
    gemm3x_body(g_att, Wo, bo, out);
}

// ---------------------------------------------------------------------------
// Flash attention: UNCHANGED from the 1913us baseline.
// block = (b, h, 128-row q-tile), 256 threads (16x16), 8x4 fragments,
// 64-row KV tiles, online softmax, scale folded into Q load.
// smem: Qs[128][68] + Ks[64][68] + Vs[64][64] + Ps[128][68] = 103424 B.
// ---------------------------------------------------------------------------
#define QS 68  // padded stride

__global__ __launch_bounds__(256) void attn_kernel() {
    extern __shared__ float sm[];
    float* Qs = sm;                            // 128*68
    float* Ks = Qs + 128 * QS;                 // 64*68
    float* Vs = Ks + 64 * QS;                  // 64*64
    float* Ps = Vs + 64 * 64;                  // 128*68

    const int tid = threadIdx.x;
    const int tx = tid & 15;
    const int ty = tid >> 4;
    const int q0 = blockIdx.x * 128;
    const int h  = blockIdx.y;
    const int b  = blockIdx.z;
    const int base = b * SEQ * D_MODEL + h * DK;

    for (int f = tid; f < 128 * 16; f += 256) {
        int i = f >> 4, d4 = (f & 15) << 2;
        float4 qv = *(const float4*)&g_q[base + (q0 + i) * D_MODEL + d4];
        qv.x *= 0.125f; qv.y *= 0.125f; qv.z *= 0.125f; qv.w *= 0.125f;
        *(float4*)&Qs[i * QS + d4] = qv;
    }

    float acc[8][4];
    float m[8], l[8];
#pragma unroll
    for (int i = 0; i < 8; i++) {
        m[i] = -1e30f; l[i] = 0.f;
#pragma unroll
        for (int j = 0; j < 4; j++) acc[i][j] = 0.f;
    }

    for (int kt = 0; kt < SEQ / 64; kt++) {
        const int kv0 = kt * 64;
        __syncthreads();
        for (int f = tid; f < 64 * 16; f += 256) {
            int j = f >> 4, d4 = (f & 15) << 2;
            *(float4*)&Ks[j * QS + d4] =
                *(const float4*)&g_k[base + (kv0 + j) * D_MODEL + d4];
            *(float4*)&Vs[j * 64 + d4] =
                *(const float4*)&g_v[base + (kv0 + j) * D_MODEL + d4];
        }
        __syncthreads();

        float s[8][4];
#pragma unroll
        for (int i = 0; i < 8; i++)
#pragma unroll
            for (int j = 0; j < 4; j++) s[i][j] = 0.f;

#pragma unroll 4
        for (int d4 = 0; d4 < 16; d4++) {
            float4 kv[4];
#pragma unroll
            for (int j = 0; j < 4; j++)
                kv[j] = *(const float4*)&Ks[(tx + 16 * j) * QS + 4 * d4];
#pragma unroll
            for (int ic = 0; ic < 2; ic++) {
                float4 qv[4];
#pragma unroll
                for (int i = 0; i < 4; i++)
                    qv[i] = *(const float4*)&Qs[(ty + 16 * (4 * ic + i)) * QS + 4 * d4];
#pragma unroll
                for (int i = 0; i < 4; i++) {
                    int ii = 4 * ic + i;
#pragma unroll
                    for (int j = 0; j < 4; j++) {
                        s[ii][j] = fmaf(qv[i].x, kv[j].x, s[ii][j]);
                        s[ii][j] = fmaf(qv[i].y, kv[j].y, s[ii][j]);
                        s[ii][j] = fmaf(qv[i].z, kv[j].z, s[ii][j]);
                        s[ii][j] = fmaf(qv[i].w, kv[j].w, s[ii][j]);
                    }
                }
            }
        }

#pragma unroll
        for (int i = 0; i < 8; i++) {
            float mx = fmaxf(fmaxf(s[i][0], s[i][1]), fmaxf(s[i][2], s[i][3]));
#pragma unroll
            for (int o = 8; o; o >>= 1)
                mx = fmaxf(mx, __shfl_xor_sync(0xffffffffu, mx, o, 16));
            float mn = fmaxf(m[i], mx);
            float corr = __expf(m[i] - mn);
            m[i] = mn;
            float sum = 0.f;
#pragma unroll
            for (int j = 0; j < 4; j++) {
                float p = __expf(s[i][j] - mn);
                s[i][j] = p;
                sum += p;
            }
#pragma unroll
            for (int o = 8; o; o >>= 1)
                sum += __shfl_xor_sync(0xffffffffu, sum, o, 16);
            l[i] = l[i] * corr + sum;
#pragma unroll
            for (int j = 0; j < 4; j++) acc[i][j] *= corr;
        }

#pragma unroll
        for (int i = 0; i < 8; i++)
#pragma unroll
            for (int j = 0; j < 4; j++)
                Ps[(ty + 16 * i) * QS + (tx + 16 * j)] = s[i][j];
        __syncthreads();

#pragma unroll 4
        for (int j4 = 0; j4 < 16; j4++) {
            float vf[4][4];
#pragma unroll
            for (int u = 0; u < 4; u++)
#pragma unroll
                for (int j = 0; j < 4; j++)
                    vf[u][j] = Vs[(4 * j4 + u) * 64 + tx + 16 * j];
#pragma unroll
            for (int ic = 0; ic < 2; ic++) {
                float4 pv[4];
#pragma unroll
                for (int i = 0; i < 4; i++)
                    pv[i] = *(const float4*)&Ps[(ty + 16 * (4 * ic + i)) * QS + 4 * j4];
#pragma unroll
                for (int u = 0; u < 4; u++) {
#pragma unroll
                    for (int i = 0; i < 4; i++) {
                        int ii = 4 * ic + i;
                        float p = ((const float*)&pv[i])[u];
#pragma unroll
                        for (int j = 0; j < 4; j++)
                            acc[ii][j] = fmaf(p, vf[u][j], acc[ii][j]);
                    }
                }
            }
        }
        __syncthreads();
    }

#pragma unroll
    for (int i = 0; i < 8; i++) {
        float inv = 1.f / l[i];
        int r = q0 + ty + 16 * i;
#pragma unroll
        for (int j = 0; j < 4; j++)
            g_att[base + r * D_MODEL + tx + 16 * j] = acc[i][j] * inv;
    }
}

// ---------------------------------------------------------------------------
extern "C" void kernel_launch(void* const* d_in, const int* in_sizes, int n_in,
                              void* d_out, int out_size) {
    const float* query = (const float*)d_in[0];
    const float* key   = (const float*)d_in[1];
    const float* value = (const float*)d_in[2];
    const float* Wq = (const float*)d_in[3];
    const float* bq = (const float*)d_in[4];
    const float* Wk = (const float*)d_in[5];
    const float* bk = (const float*)d_in[6];
    const float* Wv = (const float*)d_in[7];
    const float* bv = (const float*)d_in[8];
    const float* Wo = (const float*)d_in[9];
    const float* bo = (const float*)d_in[10];

    const int M = in_sizes[0] / D_MODEL;  // B*S = 4096
    const int B = M / SEQ;

    dim3 g1(D_MODEL / 128, M / 128, 3);
    qkv_gemm_kernel<<<g1, 256>>>(query, key, value, Wq, bq, Wk, bk, Wv, bv);

    size_t shmem =
        (size_t)(128 * QS + 64 * QS + 64 * 64 + 128 * QS) * sizeof(float);
    cudaFuncSetAttribute(attn_kernel,
                         cudaFuncAttributeMaxDynamicSharedMemorySize,
                         (int)shmem);
    dim3 g2(SEQ / 128, N_HEAD, B);
    attn_kernel<<<g2, 256, shmem>>>();

    dim3 g3(D_MODEL / 128, M / 128, 1);
    out_gemm_kernel<<<g3, 256>>>(Wo, bo, (float*)d_out);
}

// round 13
// speedup vs baseline: 1.1681x; 1.1054x over previous
#include <cuda_runtime.h>
#include <math.h>
#include <stdint.h>

#define D_MODEL 1024
#define N_HEAD  16
#define DK      64
#define SEQ     2048
#define MAXROWS 4096

// Scratch (allocation-free rule: __device__ globals)
__device__ float g_q[MAXROWS * D_MODEL];
__device__ float g_k[MAXROWS * D_MODEL];
__device__ float g_v[MAXROWS * D_MODEL];
__device__ float g_att[MAXROWS * D_MODEL];

// ---------------------------------------------------------------------------
// tf32 helpers
// ---------------------------------------------------------------------------
__device__ __forceinline__ float tf32_rna(float x) {
    uint32_t u;
    asm("cvt.rna.tf32.f32 %0, %1;" : "=r"(u) : "f"(x));
    return __uint_as_float(u);
}

__device__ __forceinline__ void mma_tf32(float* c, const uint32_t* a,
                                         const uint32_t* b) {
    asm volatile(
        "mma.sync.aligned.m16n8k8.row.col.f32.tf32.tf32.f32 "
        "{%0,%1,%2,%3}, {%4,%5,%6,%7}, {%8,%9}, {%0,%1,%2,%3};\n"
        : "+f"(c[0]), "+f"(c[1]), "+f"(c[2]), "+f"(c[3])
        : "r"(a[0]), "r"(a[1]), "r"(a[2]), "r"(a[3]), "r"(b[0]), "r"(b[1]));
}

__device__ __forceinline__ void split_store(float* hp, float* lp, float4 v) {
    float h0 = tf32_rna(v.x), h1 = tf32_rna(v.y);
    float h2 = tf32_rna(v.z), h3 = tf32_rna(v.w);
    *(float4*)hp = make_float4(h0, h1, h2, h3);
    *(float4*)lp = make_float4(v.x - h0, v.y - h1, v.z - h2, v.w - h3);
}

// Fast exp on the FMA/ALU pipes (no MUFU). x <= ~0 expected; clamped low end.
__device__ __forceinline__ float fexp(float x) {
    float t = fmaxf(x * 1.44269504f, -126.0f);
    float fi = t + 12582912.0f;                 // 1.5*2^23: round-to-nearest
    float r = fi - 12582912.0f;                 // round(t)
    float f = t - r;                            // [-0.5, 0.5]
    int n = __float_as_int(fi) - 0x4B400000;    // (int)round(t)
    float p = 0.00133336f;
    p = fmaf(p, f, 0.00961813f);
    p = fmaf(p, f, 0.05550411f);
    p = fmaf(p, f, 0.24022651f);
    p = fmaf(p, f, 0.69314718f);
    p = fmaf(p, f, 1.0f);
    return p * __int_as_float((n + 127) << 23);
}

// ---------------------------------------------------------------------------
// 3xTF32 GEMM (unchanged from 1810us version)
// ---------------------------------------------------------------------------
#define AST 20

__device__ __forceinline__ void gemm3x_body(const float* __restrict__ A,
                                            const float* __restrict__ W,
                                            const float* __restrict__ bias,
                                            float* __restrict__ C) {
    __shared__ float Ah[128][AST], Al[128][AST];
    __shared__ float Wh[128][AST], Wl[128][AST];

    const int tid = threadIdx.x;
    const int lane = tid & 31;
    const int wid = tid >> 5;
    const int g = lane >> 2, tg = lane & 3;
    const int wr = wid >> 2;
    const int wc = wid & 3;
    const int m0 = blockIdx.y * 128;
    const int n0 = blockIdx.x * 128;

    const int r0 = tid >> 2;
    const int kq = (tid & 3) << 2;

    float acc[4][4][4];
#pragma unroll
    for (int mi = 0; mi < 4; mi++)
#pragma unroll
        for (int ni = 0; ni < 4; ni++)
#pragma unroll
            for (int r = 0; r < 4; r++) acc[mi][ni][r] = 0.f;

    const float* Ap0 = A + (m0 + r0) * D_MODEL + kq;
    const float* Ap1 = A + (m0 + r0 + 64) * D_MODEL + kq;
    const float* Wp0 = W + (n0 + r0) * D_MODEL + kq;
    const float* Wp1 = W + (n0 + r0 + 64) * D_MODEL + kq;

    float4 ra0 = *(const float4*)Ap0;
    float4 ra1 = *(const float4*)Ap1;
    float4 rw0 = *(const float4*)Wp0;
    float4 rw1 = *(const float4*)Wp1;

    const int NT = D_MODEL / 16;
    for (int kt = 0; kt < NT; kt++) {
        __syncthreads();
        split_store(&Ah[r0][kq],      &Al[r0][kq],      ra0);
        split_store(&Ah[r0 + 64][kq], &Al[r0 + 64][kq], ra1);
        split_store(&Wh[r0][kq],      &Wl[r0][kq],      rw0);
        split_store(&Wh[r0 + 64][kq], &Wl[r0 + 64][kq], rw1);
        __syncthreads();

        if (kt + 1 < NT) {
            ra0 = *(const float4*)(Ap0 + (kt + 1) * 16);
            ra1 = *(const float4*)(Ap1 + (kt + 1) * 16);
            rw0 = *(const float4*)(Wp0 + (kt + 1) * 16);
            rw1 = *(const float4*)(Wp1 + (kt + 1) * 16);
        }

#pragma unroll
        for (int ks = 0; ks < 16; ks += 8) {
            uint32_t ahi[4][4], alo[4][4];
#pragma unroll
            for (int mi = 0; mi < 4; mi++) {
                int mb = wr * 64 + mi * 16;
                ahi[mi][0] = __float_as_uint(Ah[mb + g][ks + tg]);
                ahi[mi][1] = __float_as_uint(Ah[mb + g + 8][ks + tg]);
                ahi[mi][2] = __float_as_uint(Ah[mb + g][ks + tg + 4]);
                ahi[mi][3] = __float_as_uint(Ah[mb + g + 8][ks + tg + 4]);
                alo[mi][0] = __float_as_uint(Al[mb + g][ks + tg]);
                alo[mi][1] = __float_as_uint(Al[mb + g + 8][ks + tg]);
                alo[mi][2] = __float_as_uint(Al[mb + g][ks + tg + 4]);
                alo[mi][3] = __float_as_uint(Al[mb + g + 8][ks + tg + 4]);
            }
#pragma unroll
            for (int ni = 0; ni < 4; ni++) {
                int nb = wc * 32 + ni * 8;
                uint32_t bh[2], bl[2];
                bh[0] = __float_as_uint(Wh[nb + g][ks + tg]);
                bh[1] = __float_as_uint(Wh[nb + g][ks + tg + 4]);
                bl[0] = __float_as_uint(Wl[nb + g][ks + tg]);
                bl[1] = __float_as_uint(Wl[nb + g][ks + tg + 4]);
#pragma unroll
                for (int mi = 0; mi < 4; mi++) {
                    mma_tf32(acc[mi][ni], ahi[mi], bh);
                    mma_tf32(acc[mi][ni], ahi[mi], bl);
                    mma_tf32(acc[mi][ni], alo[mi], bh);
                }
            }
        }
    }

#pragma unroll
    for (int mi = 0; mi < 4; mi++) {
        int row = m0 + wr * 64 + mi * 16 + g;
#pragma unroll
        for (int ni = 0; ni < 4; ni++) {
            int col = n0 + wc * 32 + ni * 8 + 2 * tg;
            float b0 = bias[col], b1 = bias[col + 1];
            float2 v0 = make_float2(acc[mi][ni][0] + b0, acc[mi][ni][1] + b1);
            float2 v1 = make_float2(acc[mi][ni][2] + b0, acc[mi][ni][3] + b1);
            *(float2*)&C[row * D_MODEL + col] = v0;
            *(float2*)&C[(row + 8) * D_MODEL + col] = v1;
        }
    }
}

__global__ __launch_bounds__(256) void qkv_gemm_kernel(
    const float* __restrict__ q_in, const float* __restrict__ k_in,
    const float* __restrict__ v_in,
    const float* __restrict__ Wq, const float* __restrict__ bq,
    const float* __restrict__ Wk, const float* __restrict__ bk,
    const float* __restrict__ Wv, const float* __restrict__ bv) {
    const float *A, *W, *bias;
    float* C;
    if (blockIdx.z == 0)      { A = q_in; W = Wq; bias = bq; C = g_q; }
    else if (blockIdx.z == 1) { A = k_in; W = Wk; bias = bk; C = g_k; }
    else                      { A = v_in; W = Wv; bias = bv; C = g_v; }
    gemm3x_body(A, W, bias, C);
}

__global__ __launch_bounds__(256) void out_gemm_kernel(
    const float* __restrict__ Wo, const float* __restrict__ bo,
    float* __restrict__ out) {
    gemm3x_body(g_att, Wo, bo, out);
}

// ---------------------------------------------------------------------------
// Tensor-core flash attention. Block = (b, h, 128-row q-tile), 8 warps.
// Warp w owns q-rows [16w, 16w+16). KV tiles of 64. 3xTF32 everywhere.
// exp via FMA-pipe polynomial (fexp) -> MUFU no longer a bottleneck.
// smem strides: 68 for Q/K/P (banks 4g+tg), 72 for V (banks 8tg+g).
// Total smem = (2*128*68 + 2*64*68 + 2*64*72 + 2*128*68)*4 = 210944 B.
// ---------------------------------------------------------------------------
#define QS2 68
#define VST 72

__global__ __launch_bounds__(256) void attn_kernel() {
    extern __shared__ float sm[];
    float* Qh = sm;
    float* Ql = Qh + 128 * QS2;
    float* Kh = Ql + 128 * QS2;
    float* Kl = Kh + 64 * QS2;
    float* Vh = Kl + 64 * QS2;
    float* Vl = Vh + 64 * VST;
    float* Ph = Vl + 64 * VST;
    float* Pl = Ph + 128 * QS2;

    const int tid = threadIdx.x;
    const int lane = tid & 31;
    const int wid = tid >> 5;
    const int g = lane >> 2, tg = lane & 3;
    const int mb = wid * 16;          // this warp's q-row base within tile
    const int q0 = blockIdx.x * 128;
    const int h  = blockIdx.y;
    const int b  = blockIdx.z;
    const int base = b * SEQ * D_MODEL + h * DK;

    // Load Q tile (128x64), fold softmax scale, split hi/lo
    for (int f = tid; f < 128 * 16; f += 256) {
        int i = f >> 4, d4 = (f & 15) << 2;
        float4 qv = *(const float4*)&g_q[base + (q0 + i) * D_MODEL + d4];
        qv.x *= 0.125f; qv.y *= 0.125f; qv.z *= 0.125f; qv.w *= 0.125f;
        split_store(&Qh[i * QS2 + d4], &Ql[i * QS2 + d4], qv);
    }

    float o[8][4];
    float m0 = -1e30f, m1 = -1e30f, l0 = 0.f, l1 = 0.f;
#pragma unroll
    for (int n = 0; n < 8; n++)
#pragma unroll
        for (int j = 0; j < 4; j++) o[n][j] = 0.f;

    for (int kt = 0; kt < SEQ / 64; kt++) {
        const int kv0 = kt * 64;
        __syncthreads();  // prev tile's MMAs done; also covers Q-store at kt=0
        for (int f = tid; f < 64 * 16; f += 256) {
            int j = f >> 4, d4 = (f & 15) << 2;
            split_store(&Kh[j * QS2 + d4], &Kl[j * QS2 + d4],
                        *(const float4*)&g_k[base + (kv0 + j) * D_MODEL + d4]);
            split_store(&Vh[j * VST + d4], &Vl[j * VST + d4],
                        *(const float4*)&g_v[base + (kv0 + j) * D_MODEL + d4]);
        }
        __syncthreads();

        // ---- S = (Q*scale) @ K^T  (warp: 16 q-rows x 64 kv-cols) ----
        float s[8][4];
#pragma unroll
        for (int n = 0; n < 8; n++)
#pragma unroll
            for (int j = 0; j < 4; j++) s[n][j] = 0.f;

#pragma unroll
        for (int ks = 0; ks < 64; ks += 8) {
            uint32_t ah[4], al[4];
            ah[0] = __float_as_uint(Qh[(mb + g) * QS2 + ks + tg]);
            ah[1] = __float_as_uint(Qh[(mb + g + 8) * QS2 + ks + tg]);
            ah[2] = __float_as_uint(Qh[(mb + g) * QS2 + ks + tg + 4]);
            ah[3] = __float_as_uint(Qh[(mb + g + 8) * QS2 + ks + tg + 4]);
            al[0] = __float_as_uint(Ql[(mb + g) * QS2 + ks + tg]);
            al[1] = __float_as_uint(Ql[(mb + g + 8) * QS2 + ks + tg]);
            al[2] = __float_as_uint(Ql[(mb + g) * QS2 + ks + tg + 4]);
            al[3] = __float_as_uint(Ql[(mb + g + 8) * QS2 + ks + tg + 4]);
#pragma unroll
            for (int n = 0; n < 8; n++) {
                int nb = n * 8;
                uint32_t bh[2], bl[2];
                bh[0] = __float_as_uint(Kh[(nb + g) * QS2 + ks + tg]);
                bh[1] = __float_as_uint(Kh[(nb + g) * QS2 + ks + tg + 4]);
                bl[0] = __float_as_uint(Kl[(nb + g) * QS2 + ks + tg]);
                bl[1] = __float_as_uint(Kl[(nb + g) * QS2 + ks + tg + 4]);
                mma_tf32(s[n], ah, bh);
                mma_tf32(s[n], ah, bl);
                mma_tf32(s[n], al, bh);
            }
        }

        // ---- online softmax (rows g and g+8; quad-local reductions) ----
        float mx0 = -1e30f, mx1 = -1e30f;
#pragma unroll
        for (int n = 0; n < 8; n++) {
            mx0 = fmaxf(mx0, fmaxf(s[n][0], s[n][1]));
            mx1 = fmaxf(mx1, fmaxf(s[n][2], s[n][3]));
        }
        mx0 = fmaxf(mx0, __shfl_xor_sync(0xffffffffu, mx0, 1));
        mx0 = fmaxf(mx0, __shfl_xor_sync(0xffffffffu, mx0, 2));
        mx1 = fmaxf(mx1, __shfl_xor_sync(0xffffffffu, mx1, 1));
        mx1 = fmaxf(mx1, __shfl_xor_sync(0xffffffffu, mx1, 2));

        float mn0 = fmaxf(m0, mx0), mn1 = fmaxf(m1, mx1);
        float corr0 = fexp(m0 - mn0), corr1 = fexp(m1 - mn1);
        m0 = mn0; m1 = mn1;

        float sum0 = 0.f, sum1 = 0.f;
#pragma unroll
        for (int n = 0; n < 8; n++) {
            float p0 = fexp(s[n][0] - mn0); s[n][0] = p0; sum0 += p0;
            float p1 = fexp(s[n][1] - mn0); s[n][1] = p1; sum0 += p1;
            float p2 = fexp(s[n][2] - mn1); s[n][2] = p2; sum1 += p2;
            float p3 = fexp(s[n][3] - mn1); s[n][3] = p3; sum1 += p3;
        }
        sum0 += __shfl_xor_sync(0xffffffffu, sum0, 1);
        sum0 += __shfl_xor_sync(0xffffffffu, sum0, 2);
        sum1 += __shfl_xor_sync(0xffffffffu, sum1, 1);
        sum1 += __shfl_xor_sync(0xffffffffu, sum1, 2);
        l0 = l0 * corr0 + sum0;
        l1 = l1 * corr1 + sum1;

#pragma unroll
        for (int n = 0; n < 8; n++) {
            o[n][0] *= corr0; o[n][1] *= corr0;
            o[n][2] *= corr1; o[n][3] *= corr1;
        }

        // ---- store P (hi/lo) to this warp's private rows of Ph/Pl ----
#pragma unroll
        for (int n = 0; n < 8; n++) {
            int col = n * 8 + 2 * tg;
            float h0 = tf32_rna(s[n][0]), h1 = tf32_rna(s[n][1]);
            float h2 = tf32_rna(s[n][2]), h3 = tf32_rna(s[n][3]);
            *(float2*)&Ph[(mb + g) * QS2 + col] = make_float2(h0, h1);
            *(float2*)&Ph[(mb + g + 8) * QS2 + col] = make_float2(h2, h3);
            *(float2*)&Pl[(mb + g) * QS2 + col] =
                make_float2(s[n][0] - h0, s[n][1] - h1);
            *(float2*)&Pl[(mb + g + 8) * QS2 + col] =
                make_float2(s[n][2] - h2, s[n][3] - h3);
        }
        __syncwarp();

        // ---- O += P @ V  (k-dim = kv 64; V rows = kv, cols = dk) ----
#pragma unroll
        for (int ks = 0; ks < 64; ks += 8) {
            uint32_t ph[4], pl[4];
            ph[0] = __float_as_uint(Ph[(mb + g) * QS2 + ks + tg]);
            ph[1] = __float_as_uint(Ph[(mb + g + 8) * QS2 + ks + tg]);
            ph[2] = __float_as_uint(Ph[(mb + g) * QS2 + ks + tg + 4]);
            ph[3] = __float_as_uint(Ph[(mb + g + 8) * QS2 + ks + tg + 4]);
            pl[0] = __float_as_uint(Pl[(mb + g) * QS2 + ks + tg]);
            pl[1] = __float_as_uint(Pl[(mb + g + 8) * QS2 + ks + tg]);
            pl[2] = __float_as_uint(Pl[(mb + g) * QS2 + ks + tg + 4]);
            pl[3] = __float_as_uint(Pl[(mb + g + 8) * QS2 + ks + tg + 4]);
#pragma unroll
            for (int n = 0; n < 8; n++) {
                int nb = n * 8;
                uint32_t bh[2], bl[2];
                bh[0] = __float_as_uint(Vh[(ks + tg) * VST + nb + g]);
                bh[1] = __float_as_uint(Vh[(ks + tg + 4) * VST + nb + g]);
                bl[0] = __float_as_uint(Vl[(ks + tg) * VST + nb + g]);
                bl[1] = __float_as_uint(Vl[(ks + tg + 4) * VST + nb + g]);
                mma_tf32(o[n], ph, bh);
                mma_tf32(o[n], ph, bl);
                mma_tf32(o[n], pl, bh);
            }
        }
    }

    // ---- normalize + store ----
    float inv0 = 1.f / l0, inv1 = 1.f / l1;
    int r0g = q0 + mb + g;
#pragma unroll
    for (int n = 0; n < 8; n++) {
        int col = n * 8 + 2 * tg;
        *(float2*)&g_att[base + r0g * D_MODEL + col] =
            make_float2(o[n][0] * inv0, o[n][1] * inv0);
        *(float2*)&g_att[base + (r0g + 8) * D_MODEL + col] =
            make_float2(o[n][2] * inv1, o[n][3] * inv1);
    }
}

// ---------------------------------------------------------------------------
extern "C" void kernel_launch(void* const* d_in, const int* in_sizes, int n_in,
                              void* d_out, int out_size) {
    const float* query = (const float*)d_in[0];
    const float* key   = (const float*)d_in[1];
    const float* value = (const float*)d_in[2];
    const float* Wq = (const float*)d_in[3];
    const float* bq = (const float*)d_in[4];
    const float* Wk = (const float*)d_in[5];
    const float* bk = (const float*)d_in[6];
    const float* Wv = (const float*)d_in[7];
    const float* bv = (const float*)d_in[8];
    const float* Wo = (const float*)d_in[9];
    const float* bo = (const float*)d_in[10];

    const int M = in_sizes[0] / D_MODEL;  // B*S = 4096
    const int B = M / SEQ;

    dim3 g1(D_MODEL / 128, M / 128, 3);
    qkv_gemm_kernel<<<g1, 256>>>(query, key, value, Wq, bq, Wk, bk, Wv, bv);

    size_t shmem =
        (size_t)(2 * 128 * QS2 + 2 * 64 * QS2 + 2 * 64 * VST + 2 * 128 * QS2) *
        sizeof(float);  // 210944 B
    cudaFuncSetAttribute(attn_kernel,
                         cudaFuncAttributeMaxDynamicSharedMemorySize,
                         (int)shmem);
    dim3 g2(SEQ / 128, N_HEAD, B);
    attn_kernel<<<g2, 256, shmem>>>();

    dim3 g3(D_MODEL / 128, M / 128, 1);
    out_gemm_kernel<<<g3, 256>>>(Wo, bo, (float*)d_out);
}

// round 17
// speedup vs baseline: 1.9778x; 1.6932x over previous
#include <cuda_runtime.h>
#include <cuda_bf16.h>
#include <math.h>
#include <stdint.h>

#define D_MODEL 1024
#define N_HEAD  16
#define DK      64
#define SEQ     2048
#define MAXROWS 4096

// Scratch (allocation-free rule: __device__ globals)
__device__ float g_q[MAXROWS * D_MODEL];
__device__ float g_k[MAXROWS * D_MODEL];
__device__ float g_v[MAXROWS * D_MODEL];
__device__ float g_att[MAXROWS * D_MODEL];

// ---------------------------------------------------------------------------
// bf16 helpers
// ---------------------------------------------------------------------------
__device__ __forceinline__ uint32_t bf2(float lo, float hi) {
    __nv_bfloat162 t = __floats2bfloat162_rn(lo, hi);  // x=lo half, y=hi half
    return *reinterpret_cast<uint32_t*>(&t);
}

// split pair (a,b) -> hi word {bf16(a),bf16(b)}, lo word {residuals}
__device__ __forceinline__ void bsplit_pair(uint32_t* h, uint32_t* l,
                                            float a, float b) {
    float ha = __bfloat162float(__float2bfloat16(a));
    float hb = __bfloat162float(__float2bfloat16(b));
    *h = bf2(ha, hb);
    *l = bf2(a - ha, b - hb);
}

// split float4 (4 consecutive k) into 2 hi + 2 lo packed words
__device__ __forceinline__ void bsplit4(uint32_t* h, uint32_t* l, float4 v) {
    bsplit_pair(&h[0], &l[0], v.x, v.y);
    bsplit_pair(&h[1], &l[1], v.z, v.w);
}

__device__ __forceinline__ void mma_bf16(float* c, const uint32_t* a,
                                         const uint32_t* b) {
    asm volatile(
        "mma.sync.aligned.m16n8k16.row.col.f32.bf16.bf16.f32 "
        "{%0,%1,%2,%3}, {%4,%5,%6,%7}, {%8,%9}, {%0,%1,%2,%3};\n"
        : "+f"(c[0]), "+f"(c[1]), "+f"(c[2]), "+f"(c[3])
        : "r"(a[0]), "r"(a[1]), "r"(a[2]), "r"(a[3]), "r"(b[0]), "r"(b[1]));
}

// Fast exp on the FMA/ALU pipes (no MUFU).
__device__ __forceinline__ float fexp(float x) {
    float t = fmaxf(x * 1.44269504f, -126.0f);
    float fi = t + 12582912.0f;
    float r = fi - 12582912.0f;
    float f = t - r;
    int n = __float_as_int(fi) - 0x4B400000;
    float p = 0.00133336f;
    p = fmaf(p, f, 0.00961813f);
    p = fmaf(p, f, 0.05550411f);
    p = fmaf(p, f, 0.24022651f);
    p = fmaf(p, f, 0.69314718f);
    p = fmaf(p, f, 1.0f);
    return p * __int_as_float((n + 127) << 23);
}

// ---------------------------------------------------------------------------
// 3xBF16 GEMM: C[M,N] = A[M,K] @ W[N,K]^T + bias, N=K=1024.
// BM=BN=128, BK=16 (1 m16n8k16 window per tile), 8 warps (2x4), warp 64x32.
// smem words: [row][kpair] stride 12 (8 kpairs + 4 pad; banks (12g+tg)%32 ok).
// ---------------------------------------------------------------------------
#define GST 12

__device__ __forceinline__ void gemm_bf16_body(const float* __restrict__ A,
                                               const float* __restrict__ W,
                                               const float* __restrict__ bias,
                                               float* __restrict__ C) {
    __shared__ uint32_t Ahs[128][GST], Als[128][GST];
    __shared__ uint32_t Whs[128][GST], Wls[128][GST];

    const int tid = threadIdx.x;
    const int lane = tid & 31;
    const int wid = tid >> 5;
    const int g = lane >> 2, tg = lane & 3;
    const int wr = wid >> 2;
    const int wc = wid & 3;
    const int m0 = blockIdx.y * 128;
    const int n0 = blockIdx.x * 128;

    const int r0 = tid >> 1;          // 0..127
    const int kh = tid & 1;           // half (8 floats)
    const int kw = kh * 4;            // kpair word base

    float acc[4][4][4];
#pragma unroll
    for (int mi = 0; mi < 4; mi++)
#pragma unroll
        for (int ni = 0; ni < 4; ni++)
#pragma unroll
            for (int r = 0; r < 4; r++) acc[mi][ni][r] = 0.f;

    const float* Ap = A + (m0 + r0) * D_MODEL + kh * 8;
    const float* Wp = W + (n0 + r0) * D_MODEL + kh * 8;

    float4 ra0 = *(const float4*)Ap;
    float4 ra1 = *(const float4*)(Ap + 4);
    float4 rw0 = *(const float4*)Wp;
    float4 rw1 = *(const float4*)(Wp + 4);

    const int NT = D_MODEL / 16;  // 64
    for (int kt = 0; kt < NT; kt++) {
        __syncthreads();
        {
            uint32_t h0[2], l0[2], h1[2], l1[2];
            bsplit4(h0, l0, ra0); bsplit4(h1, l1, ra1);
            *(uint4*)&Ahs[r0][kw] = make_uint4(h0[0], h0[1], h1[0], h1[1]);
            *(uint4*)&Als[r0][kw] = make_uint4(l0[0], l0[1], l1[0], l1[1]);
            bsplit4(h0, l0, rw0); bsplit4(h1, l1, rw1);
            *(uint4*)&Whs[r0][kw] = make_uint4(h0[0], h0[1], h1[0], h1[1]);
            *(uint4*)&Wls[r0][kw] = make_uint4(l0[0], l0[1], l1[0], l1[1]);
        }
        __syncthreads();

        if (kt + 1 < NT) {
            ra0 = *(const float4*)(Ap + (kt + 1) * 16);
            ra1 = *(const float4*)(Ap + (kt + 1) * 16 + 4);
            rw0 = *(const float4*)(Wp + (kt + 1) * 16);
            rw1 = *(const float4*)(Wp + (kt + 1) * 16 + 4);
        }

        uint32_t ahi[4][4], alo[4][4];
#pragma unroll
        for (int mi = 0; mi < 4; mi++) {
            int mbr = wr * 64 + mi * 16;
            ahi[mi][0] = Ahs[mbr + g][tg];
            ahi[mi][1] = Ahs[mbr + g + 8][tg];
            ahi[mi][2] = Ahs[mbr + g][tg + 4];
            ahi[mi][3] = Ahs[mbr + g + 8][tg + 4];
            alo[mi][0] = Als[mbr + g][tg];
            alo[mi][1] = Als[mbr + g + 8][tg];
            alo[mi][2] = Als[mbr + g][tg + 4];
            alo[mi][3] = Als[mbr + g + 8][tg + 4];
        }
#pragma unroll
        for (int ni = 0; ni < 4; ni++) {
            int nbr = wc * 32 + ni * 8;
            uint32_t bh[2], bl[2];
            bh[0] = Whs[nbr + g][tg];
            bh[1] = Whs[nbr + g][tg + 4];
            bl[0] = Wls[nbr + g][tg];
            bl[1] = Wls[nbr + g][tg + 4];
#pragma unroll
            for (int mi = 0; mi < 4; mi++) {
                mma_bf16(acc[mi][ni], ahi[mi], bh);
                mma_bf16(acc[mi][ni], ahi[mi], bl);
                mma_bf16(acc[mi][ni], alo[mi], bh);
            }
        }
    }

#pragma unroll
    for (int mi = 0; mi < 4; mi++) {
        int row = m0 + wr * 64 + mi * 16 + g;
#pragma unroll
        for (int ni = 0; ni < 4; ni++) {
            int col = n0 + wc * 32 + ni * 8 + 2 * tg;
            float b0 = bias[col], b1 = bias[col + 1];
            float2 v0 = make_float2(acc[mi][ni][0] + b0, acc[mi][ni][1] + b1);
            float2 v1 = make_float2(acc[mi][ni][2] + b0, acc[mi][ni][3] + b1);
            *(float2*)&C[row * D_MODEL + col] = v0;
            *(float2*)&C[(row + 8) * D_MODEL + col] = v1;
        }
    }
}

__global__ __launch_bounds__(256) void qkv_gemm_kernel(
    const float* __restrict__ q_in, const float* __restrict__ k_in,
    const float* __restrict__ v_in,
    const float* __restrict__ Wq, const float* __restrict__ bq,
    const float* __restrict__ Wk, const float* __restrict__ bk,
    const float* __restrict__ Wv, const float* __restrict__ bv) {
    const float *A, *W, *bias;
    float* C;
    if (blockIdx.z == 0)      { A = q_in; W = Wq; bias = bq; C = g_q; }
    else if (blockIdx.z == 1) { A = k_in; W = Wk; bias = bk; C = g_k; }
    else                      { A = v_in; W = Wv; bias = bv; C = g_v; }
    gemm_bf16_body(A, W, bias, C);
}

__global__ __launch_bounds__(256) void out_gemm_kernel(
    const float* __restrict__ Wo, const float* __restrict__ bo,
    float* __restrict__ out) {
    gemm_bf16_body(g_att, Wo, bo, out);
}

// ---------------------------------------------------------------------------
// 3xBF16 flash attention. Block = (b, h, 128-row q-tile), 8 warps;
// warp w owns q-rows [16w,16w+16). KV tiles of 64. m16n8k16 MMAs.
// P repacked REGISTER->REGISTER into A-fragments (C-layout == A-layout),
// so no P smem round-trip. smem 73728 B.
// Layouts (32-bit words): Q/K [row][kpair] stride 36; V [kv-pair][dk] stride 72.
// ---------------------------------------------------------------------------
#define QKS 36
#define VWS 72

__global__ __launch_bounds__(256) void attn_kernel() {
    extern __shared__ uint32_t smw[];
    uint32_t* Qhs = smw;                  // 128*36
    uint32_t* Qls = Qhs + 128 * QKS;
    uint32_t* Khs = Qls + 128 * QKS;      // 64*36
    uint32_t* Kls = Khs + 64 * QKS;
    uint32_t* Vhs = Kls + 64 * QKS;       // 32*72
    uint32_t* Vls = Vhs + 32 * VWS;

    const int tid = threadIdx.x;
    const int lane = tid & 31;
    const int wid = tid >> 5;
    const int g = lane >> 2, tg = lane & 3;
    const int mb = wid * 16;
    const int q0 = blockIdx.x * 128;
    const int h  = blockIdx.y;
    const int b  = blockIdx.z;
    const int base = b * SEQ * D_MODEL + h * DK;

    // Load Q tile (128x64), fold softmax scale, split to bf16 hi/lo
    for (int f = tid; f < 128 * 16; f += 256) {
        int i = f >> 4, d4 = (f & 15) << 2;
        float4 qv = *(const float4*)&g_q[base + (q0 + i) * D_MODEL + d4];
        qv.x *= 0.125f; qv.y *= 0.125f; qv.z *= 0.125f; qv.w *= 0.125f;
        uint32_t hw[2], lw[2];
        bsplit4(hw, lw, qv);
        int kp = d4 >> 1;
        *(uint2*)&Qhs[i * QKS + kp] = make_uint2(hw[0], hw[1]);
        *(uint2*)&Qls[i * QKS + kp] = make_uint2(lw[0], lw[1]);
    }

    float o[8][4];
    float m0 = -1e30f, m1 = -1e30f, l0 = 0.f, l1 = 0.f;
#pragma unroll
    for (int n = 0; n < 8; n++)
#pragma unroll
        for (int j = 0; j < 4; j++) o[n][j] = 0.f;

    for (int kt = 0; kt < SEQ / 64; kt++) {
        const int kv0 = kt * 64;
        __syncthreads();  // prev tile MMAs done; covers Q store at kt=0
        // K: [kv row][d kpair]
        for (int f = tid; f < 64 * 16; f += 256) {
            int j = f >> 4, d4 = (f & 15) << 2;
            float4 kv = *(const float4*)&g_k[base + (kv0 + j) * D_MODEL + d4];
            uint32_t hw[2], lw[2];
            bsplit4(hw, lw, kv);
            int kp = d4 >> 1;
            *(uint2*)&Khs[j * QKS + kp] = make_uint2(hw[0], hw[1]);
            *(uint2*)&Kls[j * QKS + kp] = make_uint2(lw[0], lw[1]);
        }
        // V: word(kp, d) = {V[2kp][d] lo, V[2kp+1][d] hi}
        for (int f = tid; f < 32 * 16; f += 256) {
            int kp = f >> 4, d4 = (f & 15) << 2;
            float4 va = *(const float4*)&g_v[base + (kv0 + 2 * kp) * D_MODEL + d4];
            float4 vb = *(const float4*)&g_v[base + (kv0 + 2 * kp + 1) * D_MODEL + d4];
            uint32_t vh[4], vl[4];
            bsplit_pair(&vh[0], &vl[0], va.x, vb.x);
            bsplit_pair(&vh[1], &vl[1], va.y, vb.y);
            bsplit_pair(&vh[2], &vl[2], va.z, vb.z);
            bsplit_pair(&vh[3], &vl[3], va.w, vb.w);
            *(uint4*)&Vhs[kp * VWS + d4] = *(uint4*)vh;
            *(uint4*)&Vls[kp * VWS + d4] = *(uint4*)vl;
        }
        __syncthreads();

        // ---- S = (Q*scale) @ K^T : 4 k16 windows over dk ----
        float s[8][4];
#pragma unroll
        for (int n = 0; n < 8; n++)
#pragma unroll
            for (int j = 0; j < 4; j++) s[n][j] = 0.f;

#pragma unroll
        for (int w = 0; w < 4; w++) {
            int kpb = w * 8;
            uint32_t ah[4], al[4];
            ah[0] = Qhs[(mb + g) * QKS + kpb + tg];
            ah[1] = Qhs[(mb + g + 8) * QKS + kpb + tg];
            ah[2] = Qhs[(mb + g) * QKS + kpb + tg + 4];
            ah[3] = Qhs[(mb + g + 8) * QKS + kpb + tg + 4];
            al[0] = Qls[(mb + g) * QKS + kpb + tg];
            al[1] = Qls[(mb + g + 8) * QKS + kpb + tg];
            al[2] = Qls[(mb + g) * QKS + kpb + tg + 4];
            al[3] = Qls[(mb + g + 8) * QKS + kpb + tg + 4];
#pragma unroll
            for (int n = 0; n < 8; n++) {
                int nb = n * 8;
                uint32_t bh[2], bl[2];
                bh[0] = Khs[(nb + g) * QKS + kpb + tg];
                bh[1] = Khs[(nb + g) * QKS + kpb + tg + 4];
                bl[0] = Kls[(nb + g) * QKS + kpb + tg];
                bl[1] = Kls[(nb + g) * QKS + kpb + tg + 4];
                mma_bf16(s[n], ah, bh);
                mma_bf16(s[n], ah, bl);
                mma_bf16(s[n], al, bh);
            }
        }

        // ---- online softmax (rows g, g+8; quad reductions) ----
        float mx0 = -1e30f, mx1 = -1e30f;
#pragma unroll
        for (int n = 0; n < 8; n++) {
            mx0 = fmaxf(mx0, fmaxf(s[n][0], s[n][1]));
            mx1 = fmaxf(mx1, fmaxf(s[n][2], s[n][3]));
        }
        mx0 = fmaxf(mx0, __shfl_xor_sync(0xffffffffu, mx0, 1));
        mx0 = fmaxf(mx0, __shfl_xor_sync(0xffffffffu, mx0, 2));
        mx1 = fmaxf(mx1, __shfl_xor_sync(0xffffffffu, mx1, 1));
        mx1 = fmaxf(mx1, __shfl_xor_sync(0xffffffffu, mx1, 2));

        float mn0 = fmaxf(m0, mx0), mn1 = fmaxf(m1, mx1);
        float corr0 = fexp(m0 - mn0), corr1 = fexp(m1 - mn1);
        m0 = mn0; m1 = mn1;

        float sum0 = 0.f, sum1 = 0.f;
#pragma unroll
        for (int n = 0; n < 8; n++) {
            float p0 = fexp(s[n][0] - mn0); s[n][0] = p0; sum0 += p0;
            float p1 = fexp(s[n][1] - mn0); s[n][1] = p1; sum0 += p1;
            float p2 = fexp(s[n][2] - mn1); s[n][2] = p2; sum1 += p2;
            float p3 = fexp(s[n][3] - mn1); s[n][3] = p3; sum1 += p3;
        }
        sum0 += __shfl_xor_sync(0xffffffffu, sum0, 1);
        sum0 += __shfl_xor_sync(0xffffffffu, sum0, 2);
        sum1 += __shfl_xor_sync(0xffffffffu, sum1, 1);
        sum1 += __shfl_xor_sync(0xffffffffu, sum1, 2);
        l0 = l0 * corr0 + sum0;
        l1 = l1 * corr1 + sum1;

#pragma unroll
        for (int n = 0; n < 8; n++) {
            o[n][0] *= corr0; o[n][1] *= corr0;
            o[n][2] *= corr1; o[n][3] *= corr1;
        }

        // ---- O += P @ V ; P A-fragments built in registers from S C-frags ----
#pragma unroll
        for (int w = 0; w < 4; w++) {
            uint32_t ph[4], pl[4];
            bsplit_pair(&ph[0], &pl[0], s[2 * w][0], s[2 * w][1]);
            bsplit_pair(&ph[1], &pl[1], s[2 * w][2], s[2 * w][3]);
            bsplit_pair(&ph[2], &pl[2], s[2 * w + 1][0], s[2 * w + 1][1]);
            bsplit_pair(&ph[3], &pl[3], s[2 * w + 1][2], s[2 * w + 1][3]);
#pragma unroll
            for (int n = 0; n < 8; n++) {
                int nb = n * 8;
                uint32_t bh[2], bl[2];
                bh[0] = Vhs[(8 * w + tg) * VWS + nb + g];
                bh[1] = Vhs[(8 * w + tg + 4) * VWS + nb + g];
                bl[0] = Vls[(8 * w + tg) * VWS + nb + g];
                bl[1] = Vls[(8 * w + tg + 4) * VWS + nb + g];
                mma_bf16(o[n], ph, bh);
                mma_bf16(o[n], ph, bl);
                mma_bf16(o[n], pl, bh);
            }
        }
    }

    // ---- normalize + store ----
    float inv0 = 1.f / l0, inv1 = 1.f / l1;
    int r0g = q0 + mb + g;
#pragma unroll
    for (int n = 0; n < 8; n++) {
        int col = n * 8 + 2 * tg;
        *(float2*)&g_att[base + r0g * D_MODEL + col] =
            make_float2(o[n][0] * inv0, o[n][1] * inv0);
        *(float2*)&g_att[base + (r0g + 8) * D_MODEL + col] =
            make_float2(o[n][2] * inv1, o[n][3] * inv1);
    }
}

// ---------------------------------------------------------------------------
extern "C" void kernel_launch(void* const* d_in, const int* in_sizes, int n_in,
                              void* d_out, int out_size) {
    const float* query = (const float*)d_in[0];
    const float* key   = (const float*)d_in[1];
    const float* value = (const float*)d_in[2];
    const float* Wq = (const float*)d_in[3];
    const float* bq = (const float*)d_in[4];
    const float* Wk = (const float*)d_in[5];
    const float* bk = (const float*)d_in[6];
    const float* Wv = (const float*)d_in[7];
    const float* bv = (const float*)d_in[8];
    const float* Wo = (const float*)d_in[9];
    const float* bo = (const float*)d_in[10];

    const int M = in_sizes[0] / D_MODEL;  // B*S = 4096
    const int B = M / SEQ;

    dim3 g1(D_MODEL / 128, M / 128, 3);
    qkv_gemm_kernel<<<g1, 256>>>(query, key, value, Wq, bq, Wk, bk, Wv, bv);

    size_t shmem =
        (size_t)(2 * 128 * QKS + 2 * 64 * QKS + 2 * 32 * VWS) * 4;  // 73728 B
    cudaFuncSetAttribute(attn_kernel,
                         cudaFuncAttributeMaxDynamicSharedMemorySize,
                         (int)shmem);
    dim3 g2(SEQ / 128, N_HEAD, B);
    attn_kernel<<<g2, 256, shmem>>>();

    dim3 g3(D_MODEL / 128, M / 128, 1);
    out_gemm_kernel<<<g3, 256>>>(Wo, bo, (float*)d_out);
}